// round 3
// baseline (speedup 1.0000x reference)
#include <cuda_runtime.h>
#include <cstdint>

// ---------------------------------------------------------------------------
// Problem: out[b,o,h,w] = sum_c input[b,c,h,w]*weight[o,c] + bias[o] + s[b,o,h,w]
// where s = dwt(upsample(iwt(skip))), all Haar/blur ops folded analytically.
//
// input : [16,256,128,128] f32   weight: [12,256]   bias: [12]
// skip  : [16,12,64,64]    f32   out   : [16,12,128,128] f32
// ---------------------------------------------------------------------------

#define B_N   16
#define C_IN  256
#define C_OUT 12
#define H_    128
#define W_    128
#define HW    (H_ * W_)          // 16384
#define SH    64                 // skip spatial
#define SHW   (SH * SH)          // 4096

// scratch for s = dwt(upsample(iwt(skip)))  : 16*12*128*128 floats = 12.6 MB
__device__ float g_s[B_N * C_OUT * HW];

// ---------------------------------------------------------------------------
// Wavelet kernel.
//
// Derivation (verified against upfirdn2d semantics):
//  iwt:  t1[2m+pi, 2n+pj] = 0.5*( ll + sL*lh + sH*hl + sL*sH*hh )[m,n]
//        with sL = (pi? -1:+1), sH = (pj? -1:+1)            (t1: 128x128, 3ch)
//  upsample (blur [1,3,3,1], up2, pad(2,1,2,1)):  separable per axis:
//        t2[2p]   = (1*t1[p-1] + 3*t1[p]) / 4
//        t2[2p+1] = (3*t1[p]   + 1*t1[p+1]) / 4               (t2: 256x256)
//  dwt (2x2 Haar, down2): per output (m,n) take t2 block
//        A=t2[2m,2n] B=t2[2m,2n+1] C=t2[2m+1,2n] D=t2[2m+1,2n+1]
//        s_ll=.5(A+B+C+D) s_lh=.5(A+B-C-D) s_hl=.5(A-B+C-D) s_hh=.5(A-B-C+D)
//
// Each thread: one (b, ch in 0..2, m, n); needs 3x3 t1 patch = 2x2 skip patch
// over 4 bands (16 loads, heavily L1/L2 shared).
// ---------------------------------------------------------------------------
__global__ __launch_bounds__(256) void wavelet_kernel(
    const float* __restrict__ skip)
{
    int idx = blockIdx.x * 256 + threadIdx.x;      // 16*3*128*128 = 786432
    int n  = idx & 127;
    int m  = (idx >> 7) & 127;
    int ch = (idx >> 14) % 3;
    int b  = idx / (3 * HW);

    int rbase = (m - 1) >> 1;                      // arithmetic shift: floor
    int cbase = (n - 1) >> 1;

    const float* sk = skip + ((size_t)b * 12 + ch) * SHW;

    // 2x2 skip patch for each of the 4 bands (ll, lh, hl, hh = ch, ch+3, ch+6, ch+9)
    float ll00, ll01, ll10, ll11;
    float lh00, lh01, lh10, lh11;
    float hl00, hl01, hl10, hl11;
    float hh00, hh01, hh10, hh11;
    {
        int r0 = rbase, r1 = rbase + 1, c0 = cbase, c1 = cbase + 1;
        bool vr0 = (unsigned)r0 < 64u, vr1 = (unsigned)r1 < 64u;
        bool vc0 = (unsigned)c0 < 64u, vc1 = (unsigned)c1 < 64u;
        #define LD(band, off) \
            band##00 = (vr0 && vc0) ? sk[(off)*3*SHW + r0*SH + c0] : 0.f; \
            band##01 = (vr0 && vc1) ? sk[(off)*3*SHW + r0*SH + c1] : 0.f; \
            band##10 = (vr1 && vc0) ? sk[(off)*3*SHW + r1*SH + c0] : 0.f; \
            band##11 = (vr1 && vc1) ? sk[(off)*3*SHW + r1*SH + c1] : 0.f;
        LD(ll, 0) LD(lh, 1) LD(hl, 2) LD(hh, 3)
        #undef LD
    }

    int dm = 1 - (m & 1);   // row-within-patch for t1 row rr == m
    int dn = 1 - (n & 1);

    // t1 value at (rr, cc) with compile-time i,j in 0..2 (rr = m-1+i, cc = n-1+j)
    float t[3][3];
    #pragma unroll
    for (int i = 0; i < 3; i++) {
        #pragma unroll
        for (int j = 0; j < 3; j++) {
            int rr = m - 1 + i;
            int cc = n - 1 + j;
            int dr = (i == 0) ? 0 : (i == 2 ? 1 : dm);   // constant or dm
            int dc = (j == 0) ? 0 : (j == 2 ? 1 : dn);
            float llv = dr ? (dc ? ll11 : ll10) : (dc ? ll01 : ll00);
            float lhv = dr ? (dc ? lh11 : lh10) : (dc ? lh01 : lh00);
            float hlv = dr ? (dc ? hl11 : hl10) : (dc ? hl01 : hl00);
            float hhv = dr ? (dc ? hh11 : hh10) : (dc ? hh01 : hh00);
            float sL = (rr & 1) ? -1.f : 1.f;
            float sH = (cc & 1) ? -1.f : 1.f;
            float v = 0.5f * (llv + sL * lhv + sH * hlv + (sL * sH) * hhv);
            bool valid = ((unsigned)rr < 128u) && ((unsigned)cc < 128u);
            t[i][j] = valid ? v : 0.f;
        }
    }

    const float inv16 = 1.f / 16.f;
    float A = (t[0][0] + 3.f*t[0][1] + 3.f*t[1][0] + 9.f*t[1][1]) * inv16;
    float Bv= (3.f*t[0][1] + t[0][2] + 9.f*t[1][1] + 3.f*t[1][2]) * inv16;
    float Cv= (3.f*t[1][0] + 9.f*t[1][1] + t[2][0] + 3.f*t[2][1]) * inv16;
    float Dv= (9.f*t[1][1] + 3.f*t[1][2] + 3.f*t[2][1] + t[2][2]) * inv16;

    size_t base = ((size_t)b * C_OUT + ch) * HW + m * W_ + n;
    g_s[base            ] = 0.5f * (A + Bv + Cv + Dv);
    g_s[base + 3 * HW   ] = 0.5f * (A + Bv - Cv - Dv);
    g_s[base + 6 * HW   ] = 0.5f * (A - Bv + Cv - Dv);
    g_s[base + 9 * HW   ] = 0.5f * (A - Bv - Cv + Dv);
}

// ---------------------------------------------------------------------------
// Main kernel: per thread 4 consecutive w-pixels; 256-deep channel contraction
// with packed f32x2 FMAs. Weights duplicated (w,w) into smem once per block.
// ---------------------------------------------------------------------------
__global__ __launch_bounds__(256) void torgb_kernel(
    const float* __restrict__ input,
    const float* __restrict__ weight,
    const float* __restrict__ bias,
    float* __restrict__ out)
{
    __shared__ float2 swdup[C_IN][C_OUT];   // [c][o] = (w_oc, w_oc)  : 24 KB
    __shared__ float  sbias[C_OUT];

    int tid = threadIdx.x;
    for (int i = tid; i < C_IN * C_OUT; i += 256) {
        float w = weight[i];                // weight[o][c], i = o*256 + c
        swdup[i & 255][i >> 8] = make_float2(w, w);
    }
    if (tid < C_OUT) sbias[tid] = bias[tid];
    __syncthreads();

    int t    = blockIdx.x * 256 + tid;      // 65536 threads total
    int base = t << 2;                      // pixel index, 4 per thread
    int b    = base >> 14;
    int rem  = base & (HW - 1);

    const float4* inp = (const float4*)(input + ((size_t)b * C_IN) * HW + rem);
    // c-stride in float4 units: HW/4 = 4096

    unsigned long long a01[C_OUT], a23[C_OUT];
    #pragma unroll
    for (int o = 0; o < C_OUT; o++) { a01[o] = 0ull; a23[o] = 0ull; }

    #pragma unroll 8
    for (int c = 0; c < C_IN; c++) {
        float4 v = inp[(size_t)c * (HW / 4)];
        unsigned long long v01, v23;
        asm("mov.b64 %0, {%1, %2};" : "=l"(v01)
            : "r"(__float_as_uint(v.x)), "r"(__float_as_uint(v.y)));
        asm("mov.b64 %0, {%1, %2};" : "=l"(v23)
            : "r"(__float_as_uint(v.z)), "r"(__float_as_uint(v.w)));
        const unsigned long long* wp = (const unsigned long long*)&swdup[c][0];
        #pragma unroll
        for (int o = 0; o < C_OUT; o++) {
            unsigned long long w = wp[o];
            asm("fma.rn.f32x2 %0, %1, %2, %0;" : "+l"(a01[o]) : "l"(v01), "l"(w));
            asm("fma.rn.f32x2 %0, %1, %2, %0;" : "+l"(a23[o]) : "l"(v23), "l"(w));
        }
    }

    const float4* sp = (const float4*)(g_s + ((size_t)b * C_OUT) * HW + rem);
    float4*       op = (float4*)((float*)out + ((size_t)b * C_OUT) * HW + rem);

    #pragma unroll
    for (int o = 0; o < C_OUT; o++) {
        unsigned int xu, yu, zu, wu;
        asm("mov.b64 {%0, %1}, %2;" : "=r"(xu), "=r"(yu) : "l"(a01[o]));
        asm("mov.b64 {%0, %1}, %2;" : "=r"(zu), "=r"(wu) : "l"(a23[o]));
        float4 sv = sp[o * (HW / 4)];
        float bo = sbias[o];
        float4 r;
        r.x = __uint_as_float(xu) + bo + sv.x;
        r.y = __uint_as_float(yu) + bo + sv.y;
        r.z = __uint_as_float(zu) + bo + sv.z;
        r.w = __uint_as_float(wu) + bo + sv.w;
        op[o * (HW / 4)] = r;
    }
}

extern "C" void kernel_launch(void* const* d_in, const int* in_sizes, int n_in,
                              void* d_out, int out_size)
{
    const float* input  = (const float*)d_in[0];
    const float* skip   = (const float*)d_in[1];
    const float* weight = (const float*)d_in[2];
    const float* bias   = (const float*)d_in[3];
    float* out = (float*)d_out;

    // Kernel 1: s = dwt(upsample(iwt(skip)))  -> g_s
    wavelet_kernel<<<(B_N * 3 * HW) / 256, 256>>>(skip);

    // Kernel 2: out = W @ input + bias + g_s
    torgb_kernel<<<(B_N * HW / 4) / 256, 256>>>(input, weight, bias, out);
}

// round 4
// speedup vs baseline: 1.0184x; 1.0184x over previous
#include <cuda_runtime.h>
#include <cstdint>

// ---------------------------------------------------------------------------
// Problem: out[b,o,h,w] = sum_c input[b,c,h,w]*weight[o,c] + bias[o] + s[b,o,h,w]
// where s = dwt(upsample(iwt(skip))), all Haar/blur ops folded analytically.
//
// input : [16,256,128,128] f32   weight: [12,256]   bias: [12]
// skip  : [16,12,64,64]    f32   out   : [16,12,128,128] f32
// ---------------------------------------------------------------------------

#define B_N   16
#define C_IN  256
#define C_OUT 12
#define H_    128
#define W_    128
#define HW    (H_ * W_)          // 16384
#define SH    64                 // skip spatial
#define SHW   (SH * SH)          // 4096

// scratch for s = dwt(upsample(iwt(skip)))  : 16*12*128*128 floats = 12.6 MB
__device__ float g_s[B_N * C_OUT * HW];

// ---------------------------------------------------------------------------
// Wavelet kernel.
//
// Derivation (verified against upfirdn2d semantics):
//  iwt:  t1[2m+pi, 2n+pj] = 0.5*( ll + sL*lh + sH*hl + sL*sH*hh )[m,n]
//        with sL = (pi? -1:+1), sH = (pj? -1:+1)            (t1: 128x128, 3ch)
//  upsample (blur [1,3,3,1], up2, pad(2,1,2,1)):  separable per axis:
//        t2[2p]   = (1*t1[p-1] + 3*t1[p]) / 4
//        t2[2p+1] = (3*t1[p]   + 1*t1[p+1]) / 4               (t2: 256x256)
//  dwt (2x2 Haar, down2): per output (m,n) take t2 block
//        A=t2[2m,2n] B=t2[2m,2n+1] C=t2[2m+1,2n] D=t2[2m+1,2n+1]
//        s_ll=.5(A+B+C+D) s_lh=.5(A+B-C-D) s_hl=.5(A-B+C-D) s_hh=.5(A-B-C+D)
//
// Each thread: one (b, ch in 0..2, m, n); needs 3x3 t1 patch = 2x2 skip patch
// over 4 bands (16 loads, heavily L1/L2 shared).
// ---------------------------------------------------------------------------
__global__ __launch_bounds__(256) void wavelet_kernel(
    const float* __restrict__ skip)
{
    int idx = blockIdx.x * 256 + threadIdx.x;      // 16*3*128*128 = 786432
    int n  = idx & 127;
    int m  = (idx >> 7) & 127;
    int ch = (idx >> 14) % 3;
    int b  = idx / (3 * HW);

    int rbase = (m - 1) >> 1;                      // arithmetic shift: floor
    int cbase = (n - 1) >> 1;

    const float* sk = skip + ((size_t)b * 12 + ch) * SHW;

    // 2x2 skip patch for each of the 4 bands (ll, lh, hl, hh = ch, ch+3, ch+6, ch+9)
    float ll00, ll01, ll10, ll11;
    float lh00, lh01, lh10, lh11;
    float hl00, hl01, hl10, hl11;
    float hh00, hh01, hh10, hh11;
    {
        int r0 = rbase, r1 = rbase + 1, c0 = cbase, c1 = cbase + 1;
        bool vr0 = (unsigned)r0 < 64u, vr1 = (unsigned)r1 < 64u;
        bool vc0 = (unsigned)c0 < 64u, vc1 = (unsigned)c1 < 64u;
        #define LD(band, off) \
            band##00 = (vr0 && vc0) ? sk[(off)*3*SHW + r0*SH + c0] : 0.f; \
            band##01 = (vr0 && vc1) ? sk[(off)*3*SHW + r0*SH + c1] : 0.f; \
            band##10 = (vr1 && vc0) ? sk[(off)*3*SHW + r1*SH + c0] : 0.f; \
            band##11 = (vr1 && vc1) ? sk[(off)*3*SHW + r1*SH + c1] : 0.f;
        LD(ll, 0) LD(lh, 1) LD(hl, 2) LD(hh, 3)
        #undef LD
    }

    int dm = 1 - (m & 1);   // row-within-patch for t1 row rr == m
    int dn = 1 - (n & 1);

    // t1 value at (rr, cc) with compile-time i,j in 0..2 (rr = m-1+i, cc = n-1+j)
    float t[3][3];
    #pragma unroll
    for (int i = 0; i < 3; i++) {
        #pragma unroll
        for (int j = 0; j < 3; j++) {
            int rr = m - 1 + i;
            int cc = n - 1 + j;
            int dr = (i == 0) ? 0 : (i == 2 ? 1 : dm);   // constant or dm
            int dc = (j == 0) ? 0 : (j == 2 ? 1 : dn);
            float llv = dr ? (dc ? ll11 : ll10) : (dc ? ll01 : ll00);
            float lhv = dr ? (dc ? lh11 : lh10) : (dc ? lh01 : lh00);
            float hlv = dr ? (dc ? hl11 : hl10) : (dc ? hl01 : hl00);
            float hhv = dr ? (dc ? hh11 : hh10) : (dc ? hh01 : hh00);
            float sL = (rr & 1) ? -1.f : 1.f;
            float sH = (cc & 1) ? -1.f : 1.f;
            float v = 0.5f * (llv + sL * lhv + sH * hlv + (sL * sH) * hhv);
            bool valid = ((unsigned)rr < 128u) && ((unsigned)cc < 128u);
            t[i][j] = valid ? v : 0.f;
        }
    }

    const float inv16 = 1.f / 16.f;
    float A = (t[0][0] + 3.f*t[0][1] + 3.f*t[1][0] + 9.f*t[1][1]) * inv16;
    float Bv= (3.f*t[0][1] + t[0][2] + 9.f*t[1][1] + 3.f*t[1][2]) * inv16;
    float Cv= (3.f*t[1][0] + 9.f*t[1][1] + t[2][0] + 3.f*t[2][1]) * inv16;
    float Dv= (9.f*t[1][1] + 3.f*t[1][2] + 3.f*t[2][1] + t[2][2]) * inv16;

    size_t base = ((size_t)b * C_OUT + ch) * HW + m * W_ + n;
    g_s[base            ] = 0.5f * (A + Bv + Cv + Dv);
    g_s[base + 3 * HW   ] = 0.5f * (A + Bv - Cv - Dv);
    g_s[base + 6 * HW   ] = 0.5f * (A - Bv + Cv - Dv);
    g_s[base + 9 * HW   ] = 0.5f * (A - Bv - Cv + Dv);
}

// ---------------------------------------------------------------------------
// Main kernel: per thread 4 consecutive w-pixels; 256-deep channel contraction
// with packed f32x2 FMAs. Weights duplicated (w,w) into smem once per block.
// ---------------------------------------------------------------------------
__global__ __launch_bounds__(256) void torgb_kernel(
    const float* __restrict__ input,
    const float* __restrict__ weight,
    const float* __restrict__ bias,
    float* __restrict__ out)
{
    __shared__ float2 swdup[C_IN][C_OUT];   // [c][o] = (w_oc, w_oc)  : 24 KB
    __shared__ float  sbias[C_OUT];

    int tid = threadIdx.x;
    for (int i = tid; i < C_IN * C_OUT; i += 256) {
        float w = weight[i];                // weight[o][c], i = o*256 + c
        swdup[i & 255][i >> 8] = make_float2(w, w);
    }
    if (tid < C_OUT) sbias[tid] = bias[tid];
    __syncthreads();

    int t    = blockIdx.x * 256 + tid;      // 65536 threads total
    int base = t << 2;                      // pixel index, 4 per thread
    int b    = base >> 14;
    int rem  = base & (HW - 1);

    const float4* inp = (const float4*)(input + ((size_t)b * C_IN) * HW + rem);
    // c-stride in float4 units: HW/4 = 4096

    unsigned long long a01[C_OUT], a23[C_OUT];
    #pragma unroll
    for (int o = 0; o < C_OUT; o++) { a01[o] = 0ull; a23[o] = 0ull; }

    #pragma unroll 8
    for (int c = 0; c < C_IN; c++) {
        float4 v = inp[(size_t)c * (HW / 4)];
        unsigned long long v01, v23;
        asm("mov.b64 %0, {%1, %2};" : "=l"(v01)
            : "r"(__float_as_uint(v.x)), "r"(__float_as_uint(v.y)));
        asm("mov.b64 %0, {%1, %2};" : "=l"(v23)
            : "r"(__float_as_uint(v.z)), "r"(__float_as_uint(v.w)));
        const unsigned long long* wp = (const unsigned long long*)&swdup[c][0];
        #pragma unroll
        for (int o = 0; o < C_OUT; o++) {
            unsigned long long w = wp[o];
            asm("fma.rn.f32x2 %0, %1, %2, %0;" : "+l"(a01[o]) : "l"(v01), "l"(w));
            asm("fma.rn.f32x2 %0, %1, %2, %0;" : "+l"(a23[o]) : "l"(v23), "l"(w));
        }
    }

    const float4* sp = (const float4*)(g_s + ((size_t)b * C_OUT) * HW + rem);
    float4*       op = (float4*)((float*)out + ((size_t)b * C_OUT) * HW + rem);

    #pragma unroll
    for (int o = 0; o < C_OUT; o++) {
        unsigned int xu, yu, zu, wu;
        asm("mov.b64 {%0, %1}, %2;" : "=r"(xu), "=r"(yu) : "l"(a01[o]));
        asm("mov.b64 {%0, %1}, %2;" : "=r"(zu), "=r"(wu) : "l"(a23[o]));
        float4 sv = sp[o * (HW / 4)];
        float bo = sbias[o];
        float4 r;
        r.x = __uint_as_float(xu) + bo + sv.x;
        r.y = __uint_as_float(yu) + bo + sv.y;
        r.z = __uint_as_float(zu) + bo + sv.z;
        r.w = __uint_as_float(wu) + bo + sv.w;
        op[o * (HW / 4)] = r;
    }
}

extern "C" void kernel_launch(void* const* d_in, const int* in_sizes, int n_in,
                              void* d_out, int out_size)
{
    const float* input  = (const float*)d_in[0];
    const float* skip   = (const float*)d_in[1];
    const float* weight = (const float*)d_in[2];
    const float* bias   = (const float*)d_in[3];
    float* out = (float*)d_out;

    // Kernel 1: s = dwt(upsample(iwt(skip)))  -> g_s
    wavelet_kernel<<<(B_N * 3 * HW) / 256, 256>>>(skip);

    // Kernel 2: out = W @ input + bias + g_s
    torgb_kernel<<<(B_N * HW / 4) / 256, 256>>>(input, weight, bias, out);
}